// round 4
// baseline (speedup 1.0000x reference)
#include <cuda_runtime.h>
#include <cuda_bf16.h>
#include <cstdint>

#define SEQ 2048
#define DIM 4096
#define NH  32
#define NKV 8
#define HD  128
#define QKVN 6144   // fused projection N (4096 q + 1024 k + 1024 v)

// ---------------- scratch (device globals: no allocation allowed) ----------------
__device__ float g_xc[(size_t)SEQ * DIM];          // rna-rounded x
__device__ float g_wqkv[(size_t)QKVN * DIM];       // rna-rounded [wq;wk;wv]
__device__ float g_woc[(size_t)DIM * DIM];         // rna-rounded wo
__device__ float g_qkv[(size_t)SEQ * QKVN];        // fused q|k|v (fp32)
__device__ float g_att[(size_t)SEQ * DIM];         // attention out (rna-rounded)

__device__ __forceinline__ uint32_t cvt_tf32(float x) {
    uint32_t r;
    asm("cvt.rna.tf32.f32 %0, %1;" : "=r"(r) : "f"(x));
    return r;
}
__device__ __forceinline__ float tf32f(float x) { return __uint_as_float(cvt_tf32(x)); }
__device__ __forceinline__ void ldm4(uint32_t* r, uint32_t addr) {
    asm volatile("ldmatrix.sync.aligned.m8n8.x4.shared.b16 {%0,%1,%2,%3}, [%4];"
                 : "=r"(r[0]), "=r"(r[1]), "=r"(r[2]), "=r"(r[3]) : "r"(addr));
}
__device__ __forceinline__ void ldm2(uint32_t* r, uint32_t addr) {
    asm volatile("ldmatrix.sync.aligned.m8n8.x2.shared.b16 {%0,%1}, [%2];"
                 : "=r"(r[0]), "=r"(r[1]) : "r"(addr));
}
__device__ __forceinline__ void mma8(float* c, const uint32_t* a, uint32_t b0, uint32_t b1) {
    asm volatile("mma.sync.aligned.m16n8k8.row.col.f32.tf32.tf32.f32 "
                 "{%0,%1,%2,%3}, {%4,%5,%6,%7}, {%8,%9}, {%0,%1,%2,%3};"
                 : "+f"(c[0]), "+f"(c[1]), "+f"(c[2]), "+f"(c[3])
                 : "r"(a[0]), "r"(a[1]), "r"(a[2]), "r"(a[3]), "r"(b0), "r"(b1));
}
__device__ __forceinline__ void mma16(float* c, const uint32_t* a, uint32_t b0, uint32_t b1) {
    asm volatile("mma.sync.aligned.m16n8k16.row.col.f32.bf16.bf16.f32 "
                 "{%0,%1,%2,%3}, {%4,%5,%6,%7}, {%8,%9}, {%0,%1,%2,%3};"
                 : "+f"(c[0]), "+f"(c[1]), "+f"(c[2]), "+f"(c[3])
                 : "r"(a[0]), "r"(a[1]), "r"(a[2]), "r"(a[3]), "r"(b0), "r"(b1));
}
__device__ __forceinline__ uint32_t pack2bf(float a, float b) {
    __nv_bfloat162 t = __floats2bfloat162_rn(a, b);
    return *(uint32_t*)&t;
}
__device__ __forceinline__ float bfhi(float a) {
    return __bfloat162float(__float2bfloat16(a));
}

// ---------------- prepass: rna-round fp32 (tf32) ----------------
__global__ void cvt_rna_kernel(const float* __restrict__ in, float* __restrict__ out, int n4)
{
    int i = blockIdx.x * blockDim.x + threadIdx.x;
    if (i >= n4) return;
    float4 v = ((const float4*)in)[i];
    v.x = tf32f(v.x); v.y = tf32f(v.y); v.z = tf32f(v.z); v.w = tf32f(v.w);
    ((float4*)out)[i] = v;
}

// ---------------- TF32 NT GEMM with cp.async 3-stage: C = A * B^T ----------------
#define GSW 36
#define GSTAGE_WORDS (2 * 128 * GSW)      // A+B tile words per stage
#define GSMEM_BYTES (3 * GSTAGE_WORDS * 4)

__global__ __launch_bounds__(256, 1) void gemm_ca(const float* __restrict__ A,
                                                  const float* __restrict__ B,
                                                  float* __restrict__ C,
                                                  int M, int N, int K)
{
    extern __shared__ uint32_t sh[];
    int tid = threadIdx.x, wid = tid >> 5, lane = tid & 31;
    int warp_m = wid >> 2, warp_n = wid & 3;
    int m0 = blockIdx.y * 128, n0 = blockIdx.x * 128;
    uint32_t shb = (uint32_t)__cvta_generic_to_shared(sh);

    int lrow = tid >> 1;
    int lcolw = (tid & 1) * 16;
    const float* Ag = A + (size_t)(m0 + lrow) * K + lcolw;
    const float* Bg = B + (size_t)(n0 + lrow) * K + lcolw;
    uint32_t sdstA = shb + (uint32_t)((lrow * GSW + lcolw) << 2);
    uint32_t sdstB = sdstA + (uint32_t)(128 * GSW * 4);

    int la = lane & 15, ahi = lane >> 4;
    int rb = (lane & 7) + ((lane >> 4) << 3), bhi = (lane >> 3) & 1;
    uint32_t aab[4], bab[4];
#pragma unroll
    for (int mi = 0; mi < 4; mi++)
        aab[mi] = shb + (uint32_t)(((warp_m * 64 + mi * 16 + la) * GSW + ahi * 4) << 2);
#pragma unroll
    for (int ni = 0; ni < 4; ni++)
        bab[ni] = shb + (uint32_t)((128 * GSW + (warp_n * 32 + ni * 8 + rb) * GSW + bhi * 4) << 2);

    float acc[4][4][4];
#pragma unroll
    for (int mi = 0; mi < 4; mi++)
#pragma unroll
        for (int ni = 0; ni < 4; ni++)
#pragma unroll
            for (int t = 0; t < 4; t++) acc[mi][ni][t] = 0.0f;

    const int iters = K >> 5;

    auto issue = [&](int s, int k0) {
        uint32_t off = (uint32_t)(s * GSTAGE_WORDS * 4);
        const float* ga = Ag + k0;
        const float* gb = Bg + k0;
#pragma unroll
        for (int i = 0; i < 4; i++) {
            asm volatile("cp.async.cg.shared.global [%0], [%1], 16;"
                         :: "r"(sdstA + off + i * 16), "l"(ga + i * 4));
            asm volatile("cp.async.cg.shared.global [%0], [%1], 16;"
                         :: "r"(sdstB + off + i * 16), "l"(gb + i * 4));
        }
    };

    issue(0, 0);  asm volatile("cp.async.commit_group;");
    issue(1, 32); asm volatile("cp.async.commit_group;");

    for (int it = 0; it < iters; ++it) {
        asm volatile("cp.async.wait_group 1;");
        __syncthreads();
        if (it + 2 < iters) issue((it + 2) % 3, (it + 2) * 32);
        asm volatile("cp.async.commit_group;");

        uint32_t soff = (uint32_t)((it % 3) * GSTAGE_WORDS * 4);
#pragma unroll
        for (int ks = 0; ks < 4; ks++) {
            uint32_t af[4][4], bf2[4][2];
#pragma unroll
            for (int mi = 0; mi < 4; mi++) ldm4(af[mi], aab[mi] + soff + ks * 32);
#pragma unroll
            for (int ni = 0; ni < 4; ni++) ldm2(bf2[ni], bab[ni] + soff + ks * 32);
#pragma unroll
            for (int mi = 0; mi < 4; mi++)
#pragma unroll
                for (int ni = 0; ni < 4; ni++)
                    mma8(acc[mi][ni], af[mi], bf2[ni][0], bf2[ni][1]);
        }
    }

    int g = lane >> 2, tg = lane & 3;
#pragma unroll
    for (int mi = 0; mi < 4; mi++) {
#pragma unroll
        for (int ni = 0; ni < 4; ni++) {
            int row = m0 + warp_m * 64 + mi * 16 + g;
            int col = n0 + warp_n * 32 + ni * 8 + tg * 2;
            *(float2*)&C[(size_t)row * N + col] =
                make_float2(acc[mi][ni][0], acc[mi][ni][1]);
            *(float2*)&C[(size_t)(row + 8) * N + col] =
                make_float2(acc[mi][ni][2], acc[mi][ni][3]);
        }
    }
}

// ---------------- RoPE (interleaved pairs) on fused qkv ----------------
__global__ void rope_kernel(float* __restrict__ base, const float* __restrict__ cs,
                            const float* __restrict__ sn, int nh, int rowStride, int total)
{
    int idx = blockIdx.x * blockDim.x + threadIdx.x;
    if (idx >= total) return;
    int pr = idx & 63;
    int hh = (idx >> 6) % nh;
    int ss = idx / (64 * nh);
    float c  = cs[ss * 64 + pr];
    float si = sn[ss * 64 + pr];
    float2* p = (float2*)(base + (size_t)ss * rowStride + hh * HD + pr * 2);
    float2 ri = *p;
    float2 o;
    o.x = ri.x * c - ri.y * si;
    o.y = ri.x * si + ri.y * c;
    *p = o;
}

// ---------------- Tensor-core flash attention: bf16 3-term QK, tf32 PV ----------
// smem words (4B): QH 128x68 | QL 128x68 | KH 64x68 | KL 64x68 | VT 128x68 f32 | PS 128x76 f32
#define AQH 0
#define AQL 8704
#define AKH 17408
#define AKL 21760
#define AVT 26112
#define APS 34816
#define ATT_WORDS 44544    // 178176 bytes

__global__ __launch_bounds__(256, 1) void attn_tc(const float* __restrict__ qkv,
                                                  float* __restrict__ O)
{
    extern __shared__ float sm[];
    uint32_t* smw = (uint32_t*)sm;
    int tid = threadIdx.x, wid = tid >> 5, lane = tid & 31;
    int qt = (int)gridDim.x - 1 - (int)blockIdx.x;   // longest-first
    int h = blockIdx.y, kvh = h >> 2;
    int qm0 = qt * 128;
    const float scale = 0.08838834764831845f;   // 1/sqrt(128)
    int g = lane >> 2, tg = lane & 3;
    int wr0 = wid * 16;
    int row0 = qm0 + wr0 + g, row1 = row0 + 8;

    // Q tile: scaled, hi/lo bf16 packed
    for (int i = tid; i < 128 * 32; i += 256) {
        int r = i >> 5, c4 = (i & 31) << 2;
        float4 qv = *(const float4*)&qkv[(size_t)(qm0 + r) * QKVN + h * HD + c4];
        qv.x *= scale; qv.y *= scale; qv.z *= scale; qv.w *= scale;
        float hx = bfhi(qv.x), hy = bfhi(qv.y), hz = bfhi(qv.z), hw = bfhi(qv.w);
        int w = r * 68 + (c4 >> 1);
        smw[AQH + w]     = pack2bf(hx, hy);
        smw[AQH + w + 1] = pack2bf(hz, hw);
        smw[AQL + w]     = pack2bf(qv.x - hx, qv.y - hy);
        smw[AQL + w + 1] = pack2bf(qv.z - hz, qv.w - hw);
    }

    uint32_t shb = (uint32_t)__cvta_generic_to_shared(sm);
    int la = lane & 15, hiq = lane >> 4;
    uint32_t aQH = shb + (uint32_t)((AQH + (wr0 + la) * 68 + hiq * 4) << 2);
    uint32_t aQL = shb + (uint32_t)((AQL + (wr0 + la) * 68 + hiq * 4) << 2);
    uint32_t bKH = shb + (uint32_t)((AKH + la * 68 + hiq * 4) << 2);
    uint32_t bKL = shb + (uint32_t)((AKL + la * 68 + hiq * 4) << 2);
    uint32_t aP  = shb + (uint32_t)((APS + (wr0 + la) * 76 + hiq * 4) << 2);
    int rbv = (lane & 7) + ((lane >> 4) << 3), bhiv = (lane >> 3) & 1;
    uint32_t bV = shb + (uint32_t)((AVT + rbv * 68 + bhiv * 4) << 2);

    float oa[16][4];
#pragma unroll
    for (int i = 0; i < 16; i++)
#pragma unroll
        for (int j = 0; j < 4; j++) oa[i][j] = 0.0f;
    float m0 = -1e30f, m1 = -1e30f, l0 = 0.0f, l1 = 0.0f;

    int ktmax = 2 * qt + 1;
    for (int kt = 0; kt <= ktmax; kt++) {
        int kn0 = kt * 64;
        __syncthreads();
        // K hi/lo + V transposed (tf32)
        for (int i = tid; i < 64 * 32; i += 256) {
            int r = i >> 5, c4 = (i & 31) << 2;
            float4 kv = *(const float4*)&qkv[(size_t)(kn0 + r) * QKVN + DIM + kvh * HD + c4];
            float hx = bfhi(kv.x), hy = bfhi(kv.y), hz = bfhi(kv.z), hw = bfhi(kv.w);
            int w = r * 68 + (c4 >> 1);
            smw[AKH + w]     = pack2bf(hx, hy);
            smw[AKH + w + 1] = pack2bf(hz, hw);
            smw[AKL + w]     = pack2bf(kv.x - hx, kv.y - hy);
            smw[AKL + w + 1] = pack2bf(kv.z - hz, kv.w - hw);
            float4 vv = *(const float4*)&qkv[(size_t)(kn0 + r) * QKVN + DIM + NKV * HD + kvh * HD + c4];
            sm[AVT + (c4 + 0) * 68 + r] = tf32f(vv.x);
            sm[AVT + (c4 + 1) * 68 + r] = tf32f(vv.y);
            sm[AVT + (c4 + 2) * 68 + r] = tf32f(vv.z);
            sm[AVT + (c4 + 3) * 68 + r] = tf32f(vv.w);
        }
        __syncthreads();

        if (qm0 + wr0 + 15 < kn0) continue;   // warp fully masked

        // ---- QK^T: bf16 hi/lo 3-term ----
        float sc[8][4];
#pragma unroll
        for (int i = 0; i < 8; i++)
#pragma unroll
            for (int j = 0; j < 4; j++) sc[i][j] = 0.0f;

#pragma unroll 2
        for (int ks = 0; ks < 8; ks++) {
            uint32_t ah[4], al[4];
            ldm4(ah, aQH + ks * 32);
            ldm4(al, aQL + ks * 32);
#pragma unroll
            for (int npp = 0; npp < 4; npp++) {
                uint32_t bh[4], bl[4];
                ldm4(bh, bKH + (uint32_t)(npp * 16 * 68 * 4) + ks * 32);
                ldm4(bl, bKL + (uint32_t)(npp * 16 * 68 * 4) + ks * 32);
                mma16(sc[2 * npp],     ah, bh[0], bh[2]);
                mma16(sc[2 * npp],     al, bh[0], bh[2]);
                mma16(sc[2 * npp],     ah, bl[0], bl[2]);
                mma16(sc[2 * npp + 1], ah, bh[1], bh[3]);
                mma16(sc[2 * npp + 1], al, bh[1], bh[3]);
                mma16(sc[2 * npp + 1], ah, bl[1], bl[3]);
            }
        }

        // causal mask on diagonal tiles
        if (kt >= 2 * qt) {
#pragma unroll
            for (int nf = 0; nf < 8; nf++) {
                int kc = kn0 + nf * 8 + 2 * tg;
                if (kc > row0)     sc[nf][0] = -1e30f;
                if (kc + 1 > row0) sc[nf][1] = -1e30f;
                if (kc > row1)     sc[nf][2] = -1e30f;
                if (kc + 1 > row1) sc[nf][3] = -1e30f;
            }
        }

        // ---- online softmax ----
        float rm0 = -1e30f, rm1 = -1e30f;
#pragma unroll
        for (int nf = 0; nf < 8; nf++) {
            rm0 = fmaxf(rm0, fmaxf(sc[nf][0], sc[nf][1]));
            rm1 = fmaxf(rm1, fmaxf(sc[nf][2], sc[nf][3]));
        }
        rm0 = fmaxf(rm0, __shfl_xor_sync(0xffffffffu, rm0, 1));
        rm0 = fmaxf(rm0, __shfl_xor_sync(0xffffffffu, rm0, 2));
        rm1 = fmaxf(rm1, __shfl_xor_sync(0xffffffffu, rm1, 1));
        rm1 = fmaxf(rm1, __shfl_xor_sync(0xffffffffu, rm1, 2));
        float mn0 = fmaxf(m0, rm0), mn1 = fmaxf(m1, rm1);
        float fac0 = __expf(m0 - mn0), fac1 = __expf(m1 - mn1);
        float rs0 = 0.0f, rs1 = 0.0f;
#pragma unroll
        for (int nf = 0; nf < 8; nf++) {
            sc[nf][0] = __expf(sc[nf][0] - mn0);
            sc[nf][1] = __expf(sc[nf][1] - mn0);
            sc[nf][2] = __expf(sc[nf][2] - mn1);
            sc[nf][3] = __expf(sc[nf][3] - mn1);
            rs0 += sc[nf][0] + sc[nf][1];
            rs1 += sc[nf][2] + sc[nf][3];
        }
        rs0 += __shfl_xor_sync(0xffffffffu, rs0, 1);
        rs0 += __shfl_xor_sync(0xffffffffu, rs0, 2);
        rs1 += __shfl_xor_sync(0xffffffffu, rs1, 1);
        rs1 += __shfl_xor_sync(0xffffffffu, rs1, 2);
        l0 = l0 * fac0 + rs0; m0 = mn0;
        l1 = l1 * fac1 + rs1; m1 = mn1;
#pragma unroll
        for (int nf = 0; nf < 16; nf++) {
            oa[nf][0] *= fac0; oa[nf][1] *= fac0;
            oa[nf][2] *= fac1; oa[nf][3] *= fac1;
        }

        // write P (tf32) to warp-private smem rows
        __syncwarp();
#pragma unroll
        for (int nf = 0; nf < 8; nf++) {
            *(float2*)&sm[APS + (wr0 + g) * 76 + nf * 8 + 2 * tg] =
                make_float2(tf32f(sc[nf][0]), tf32f(sc[nf][1]));
            *(float2*)&sm[APS + (wr0 + g + 8) * 76 + nf * 8 + 2 * tg] =
                make_float2(tf32f(sc[nf][2]), tf32f(sc[nf][3]));
        }
        __syncwarp();

        // ---- O += P @ V (tf32) ----
#pragma unroll 2
        for (int ks2 = 0; ks2 < 8; ks2++) {
            uint32_t pa[4];
            ldm4(pa, aP + ks2 * 32);
#pragma unroll
            for (int np = 0; np < 8; np++) {
                uint32_t bv[4];
                ldm4(bv, bV + (uint32_t)(np * 16 * 68 * 4) + ks2 * 32);
                mma8(oa[2 * np],     pa, bv[0], bv[1]);
                mma8(oa[2 * np + 1], pa, bv[2], bv[3]);
            }
        }
    }

    // epilogue: rna-rounded (O-proj A operand needs tf32-ready data)
    float inv0 = 1.0f / l0, inv1 = 1.0f / l1;
#pragma unroll
    for (int nf = 0; nf < 16; nf++) {
        int col = nf * 8 + 2 * tg;
        *(float2*)&O[((size_t)row0 * NH + h) * HD + col] =
            make_float2(tf32f(oa[nf][0] * inv0), tf32f(oa[nf][1] * inv0));
        *(float2*)&O[((size_t)row1 * NH + h) * HD + col] =
            make_float2(tf32f(oa[nf][2] * inv1), tf32f(oa[nf][3] * inv1));
    }
}

// ---------------- launch ----------------
extern "C" void kernel_launch(void* const* d_in, const int* in_sizes, int n_in,
                              void* d_out, int out_size)
{
    const float* x  = (const float*)d_in[0];
    const float* wq = (const float*)d_in[1];
    const float* wk = (const float*)d_in[2];
    const float* wv = (const float*)d_in[3];
    const float* wo = (const float*)d_in[4];
    const float* fc = (const float*)d_in[5];
    const float* fs = (const float*)d_in[6];
    float* out = (float*)d_out;

    float *xc, *wqkv, *woc, *qkv, *att;
    cudaGetSymbolAddress((void**)&xc,   g_xc);
    cudaGetSymbolAddress((void**)&wqkv, g_wqkv);
    cudaGetSymbolAddress((void**)&woc,  g_woc);
    cudaGetSymbolAddress((void**)&qkv,  g_qkv);
    cudaGetSymbolAddress((void**)&att,  g_att);

    // prepass: rna-round inputs (tf32 semantics preserved end-to-end)
    int t = 256;
    cvt_rna_kernel<<<(SEQ * DIM / 4 + t - 1) / t, t>>>(x, xc, SEQ * DIM / 4);
    cvt_rna_kernel<<<(DIM * DIM / 4 + t - 1) / t, t>>>(wq, wqkv, DIM * DIM / 4);
    cvt_rna_kernel<<<(NKV * HD * DIM / 4 + t - 1) / t, t>>>(wk, wqkv + (size_t)DIM * DIM, NKV * HD * DIM / 4);
    cvt_rna_kernel<<<(NKV * HD * DIM / 4 + t - 1) / t, t>>>(wv, wqkv + (size_t)(DIM + NKV * HD) * DIM, NKV * HD * DIM / 4);
    cvt_rna_kernel<<<(DIM * DIM / 4 + t - 1) / t, t>>>(wo, woc, DIM * DIM / 4);

    cudaFuncSetAttribute(gemm_ca, cudaFuncAttributeMaxDynamicSharedMemorySize, GSMEM_BYTES);
    dim3 blk(256);

    // fused QKV projection: [2048,4096] x [6144,4096]^T
    gemm_ca<<<dim3(QKVN / 128, SEQ / 128), blk, GSMEM_BYTES>>>(xc, wqkv, qkv, SEQ, QKVN, DIM);

    // RoPE on q and k sections of fused buffer
    rope_kernel<<<(SEQ * NH * 64 + 255) / 256, 256>>>(qkv, fc, fs, NH, QKVN, SEQ * NH * 64);
    rope_kernel<<<(SEQ * NKV * 64 + 255) / 256, 256>>>(qkv + DIM, fc, fs, NKV, QKVN, SEQ * NKV * 64);

    // attention
    int ash = ATT_WORDS * (int)sizeof(float);
    cudaFuncSetAttribute(attn_tc, cudaFuncAttributeMaxDynamicSharedMemorySize, ash);
    attn_tc<<<dim3(SEQ / 128, NH), blk, ash>>>(qkv, att);

    // output projection
    gemm_ca<<<dim3(DIM / 128, SEQ / 128), blk, GSMEM_BYTES>>>(att, woc, out, SEQ, DIM, DIM);
}

// round 5
// speedup vs baseline: 1.2752x; 1.2752x over previous
#include <cuda_runtime.h>
#include <cuda_bf16.h>
#include <cstdint>

#define SEQ 2048
#define DIM 4096
#define NH  32
#define NKV 8
#define HD  128
#define QKVN 6144   // fused projection N (4096 q + 1024 k + 1024 v)

// ---------------- scratch (device globals: no allocation allowed) ----------------
__device__ float g_qkv[(size_t)SEQ * QKVN];        // fused q|k|v (fp32)
__device__ float g_att[(size_t)SEQ * DIM];         // attention out

__device__ __forceinline__ uint32_t cvt_tf32(float x) {
    uint32_t r;
    asm("cvt.rna.tf32.f32 %0, %1;" : "=r"(r) : "f"(x));
    return r;
}
__device__ __forceinline__ float tf32f(float x) { return __uint_as_float(cvt_tf32(x)); }
__device__ __forceinline__ void ldm4(uint32_t* r, uint32_t addr) {
    asm volatile("ldmatrix.sync.aligned.m8n8.x4.shared.b16 {%0,%1,%2,%3}, [%4];"
                 : "=r"(r[0]), "=r"(r[1]), "=r"(r[2]), "=r"(r[3]) : "r"(addr));
}
__device__ __forceinline__ void ldm2(uint32_t* r, uint32_t addr) {
    asm volatile("ldmatrix.sync.aligned.m8n8.x2.shared.b16 {%0,%1}, [%2];"
                 : "=r"(r[0]), "=r"(r[1]) : "r"(addr));
}
__device__ __forceinline__ void mma8(float* c, const uint32_t* a, uint32_t b0, uint32_t b1) {
    asm volatile("mma.sync.aligned.m16n8k8.row.col.f32.tf32.tf32.f32 "
                 "{%0,%1,%2,%3}, {%4,%5,%6,%7}, {%8,%9}, {%0,%1,%2,%3};"
                 : "+f"(c[0]), "+f"(c[1]), "+f"(c[2]), "+f"(c[3])
                 : "r"(a[0]), "r"(a[1]), "r"(a[2]), "r"(a[3]), "r"(b0), "r"(b1));
}
__device__ __forceinline__ void mma16(float* c, const uint32_t* a, uint32_t b0, uint32_t b1) {
    asm volatile("mma.sync.aligned.m16n8k16.row.col.f32.bf16.bf16.f32 "
                 "{%0,%1,%2,%3}, {%4,%5,%6,%7}, {%8,%9}, {%0,%1,%2,%3};"
                 : "+f"(c[0]), "+f"(c[1]), "+f"(c[2]), "+f"(c[3])
                 : "r"(a[0]), "r"(a[1]), "r"(a[2]), "r"(a[3]), "r"(b0), "r"(b1));
}
__device__ __forceinline__ uint32_t pack2bf(float a, float b) {
    __nv_bfloat162 t = __floats2bfloat162_rn(a, b);
    return *(uint32_t*)&t;
}
__device__ __forceinline__ float bfhi(float a) {
    return __bfloat162float(__float2bfloat16(a));
}

// ---------------- TF32 tensor-core NT GEMM (R3 core, fused-B variant) -------------
// C[M, outN] partial: C cols [n0, n0+128) = A[M,K] * Bsel[nloc.., K]^T
// B pointer selected per block: n0 < DIM -> B0, < DIM+1024 -> B1, else B2.
#define SA 36
#define BUFE (2 * 128 * SA)

__global__ __launch_bounds__(256, 1) void gemm_tf32(const float* __restrict__ A,
                                                    const float* __restrict__ B0,
                                                    const float* __restrict__ B1,
                                                    const float* __restrict__ B2,
                                                    float* __restrict__ C,
                                                    int M, int outN, int K)
{
    extern __shared__ uint32_t sh[];
    int tid = threadIdx.x;
    int wid = tid >> 5, lane = tid & 31;
    int warp_m = wid >> 2, warp_n = wid & 3;
    int m0 = blockIdx.y * 128, n0 = blockIdx.x * 128;

    const float* Bsel;
    int nloc;
    if (n0 < DIM)                { Bsel = B0; nloc = n0; }
    else if (n0 < DIM + 1024)    { Bsel = B1; nloc = n0 - DIM; }
    else                         { Bsel = B2; nloc = n0 - DIM - 1024; }

    int lr = tid >> 3;
    int lc = (tid & 7) * 4;
    const float* Aq = A + (size_t)(m0 + lr) * K + lc;
    const float* Bq = Bsel + (size_t)(nloc + lr) * K + lc;

    float ra[4][4], rb[4][4];
    uint32_t shbase = (uint32_t)__cvta_generic_to_shared(sh);

    uint32_t a_addr[4], b_addr[4];
    {
        int la = lane & 15;
        int ahi = (lane >> 4) & 1;
#pragma unroll
        for (int mi = 0; mi < 4; mi++) {
            int r = warp_m * 64 + mi * 16 + la;
            a_addr[mi] = shbase + (uint32_t)((r * SA + ahi * 4) * 4);
        }
        int lb = lane & 7;
        int bhi = (lane >> 3) & 1;
#pragma unroll
        for (int ni = 0; ni < 4; ni++) {
            int r = warp_n * 32 + ni * 8 + lb;
            b_addr[ni] = shbase + (uint32_t)((128 * SA + r * SA + (bhi & 1) * 4) * 4);
        }
    }

    float acc[4][4][4];
#pragma unroll
    for (int mi = 0; mi < 4; mi++)
#pragma unroll
        for (int ni = 0; ni < 4; ni++)
#pragma unroll
            for (int t = 0; t < 4; t++) acc[mi][ni][t] = 0.0f;

    const int iters = K >> 5;

#pragma unroll
    for (int rr = 0; rr < 4; rr++) {
        float4 a = *(const float4*)(Aq + (size_t)rr * 32 * K);
        ra[rr][0] = a.x; ra[rr][1] = a.y; ra[rr][2] = a.z; ra[rr][3] = a.w;
        float4 b = *(const float4*)(Bq + (size_t)rr * 32 * K);
        rb[rr][0] = b.x; rb[rr][1] = b.y; rb[rr][2] = b.z; rb[rr][3] = b.w;
    }
#pragma unroll
    for (int rr = 0; rr < 4; rr++) {
        uint32_t* As = sh;
        uint32_t* Bs = sh + 128 * SA;
        uint4 av = make_uint4(cvt_tf32(ra[rr][0]), cvt_tf32(ra[rr][1]),
                              cvt_tf32(ra[rr][2]), cvt_tf32(ra[rr][3]));
        *(uint4*)&As[(lr + 32 * rr) * SA + lc] = av;
        uint4 bv = make_uint4(cvt_tf32(rb[rr][0]), cvt_tf32(rb[rr][1]),
                              cvt_tf32(rb[rr][2]), cvt_tf32(rb[rr][3]));
        *(uint4*)&Bs[(lr + 32 * rr) * SA + lc] = bv;
    }
    __syncthreads();

    for (int it = 0; it < iters; ++it) {
        int cur = it & 1;
        if (it + 1 < iters) {
            int ko = (it + 1) << 5;
#pragma unroll
            for (int rr = 0; rr < 4; rr++) {
                float4 a = *(const float4*)(Aq + (size_t)rr * 32 * K + ko);
                ra[rr][0] = a.x; ra[rr][1] = a.y; ra[rr][2] = a.z; ra[rr][3] = a.w;
                float4 b = *(const float4*)(Bq + (size_t)rr * 32 * K + ko);
                rb[rr][0] = b.x; rb[rr][1] = b.y; rb[rr][2] = b.z; rb[rr][3] = b.w;
            }
        }

        uint32_t boff = (uint32_t)(cur * BUFE * 4);
#pragma unroll
        for (int ks = 0; ks < 4; ks++) {
            uint32_t af[4][4], bf2[4][2];
#pragma unroll
            for (int mi = 0; mi < 4; mi++)
                ldm4(af[mi], a_addr[mi] + boff + ks * 32);
#pragma unroll
            for (int ni = 0; ni < 4; ni++)
                ldm2(bf2[ni], b_addr[ni] + boff + ks * 32);
#pragma unroll
            for (int mi = 0; mi < 4; mi++)
#pragma unroll
                for (int ni = 0; ni < 4; ni++)
                    mma8(acc[mi][ni], af[mi], bf2[ni][0], bf2[ni][1]);
        }

        if (it + 1 < iters) {
            uint32_t* As = sh + (cur ^ 1) * BUFE;
            uint32_t* Bs = As + 128 * SA;
#pragma unroll
            for (int rr = 0; rr < 4; rr++) {
                uint4 av = make_uint4(cvt_tf32(ra[rr][0]), cvt_tf32(ra[rr][1]),
                                      cvt_tf32(ra[rr][2]), cvt_tf32(ra[rr][3]));
                *(uint4*)&As[(lr + 32 * rr) * SA + lc] = av;
                uint4 bv = make_uint4(cvt_tf32(rb[rr][0]), cvt_tf32(rb[rr][1]),
                                      cvt_tf32(rb[rr][2]), cvt_tf32(rb[rr][3]));
                *(uint4*)&Bs[(lr + 32 * rr) * SA + lc] = bv;
            }
            __syncthreads();
        }
    }

    int g = lane >> 2, tg = lane & 3;
#pragma unroll
    for (int mi = 0; mi < 4; mi++) {
#pragma unroll
        for (int ni = 0; ni < 4; ni++) {
            int row = m0 + warp_m * 64 + mi * 16 + g;
            int col = n0 + warp_n * 32 + ni * 8 + tg * 2;
            *(float2*)&C[(size_t)row * outN + col] =
                make_float2(acc[mi][ni][0], acc[mi][ni][1]);
            *(float2*)&C[(size_t)(row + 8) * outN + col] =
                make_float2(acc[mi][ni][2], acc[mi][ni][3]);
        }
    }
}

// ---------------- RoPE (interleaved pairs) on fused qkv ----------------
__global__ void rope_kernel(float* __restrict__ base, const float* __restrict__ cs,
                            const float* __restrict__ sn, int nh, int rowStride, int total)
{
    int idx = blockIdx.x * blockDim.x + threadIdx.x;
    if (idx >= total) return;
    int pr = idx & 63;
    int hh = (idx >> 6) % nh;
    int ss = idx / (64 * nh);
    float c  = cs[ss * 64 + pr];
    float si = sn[ss * 64 + pr];
    float2* p = (float2*)(base + (size_t)ss * rowStride + hh * HD + pr * 2);
    float2 ri = *p;
    float2 o;
    o.x = ri.x * c - ri.y * si;
    o.y = ri.x * si + ri.y * c;
    *p = o;
}

// ---------------- Tensor-core flash attention: bf16 3-term QK, tf32 PV ----------
// smem words (4B): QH 128x68 | QL 128x68 | KH 64x68 | KL 64x68 | VT 128x68 f32 | PS 128x76 f32
#define AQH 0
#define AQL 8704
#define AKH 17408
#define AKL 21760
#define AVT 26112
#define APS 34816
#define ATT_WORDS 44544    // 178176 bytes

__global__ __launch_bounds__(256, 1) void attn_tc(const float* __restrict__ qkv,
                                                  float* __restrict__ O)
{
    extern __shared__ float sm[];
    uint32_t* smw = (uint32_t*)sm;
    int tid = threadIdx.x, wid = tid >> 5, lane = tid & 31;
    int qt = (int)gridDim.x - 1 - (int)blockIdx.x;   // longest-first
    int h = blockIdx.y, kvh = h >> 2;
    int qm0 = qt * 128;
    const float scale = 0.08838834764831845f;   // 1/sqrt(128)
    int g = lane >> 2, tg = lane & 3;
    int wr0 = wid * 16;
    int row0 = qm0 + wr0 + g, row1 = row0 + 8;

    // Q tile: scaled, hi/lo bf16 packed
    for (int i = tid; i < 128 * 32; i += 256) {
        int r = i >> 5, c4 = (i & 31) << 2;
        float4 qv = *(const float4*)&qkv[(size_t)(qm0 + r) * QKVN + h * HD + c4];
        qv.x *= scale; qv.y *= scale; qv.z *= scale; qv.w *= scale;
        float hx = bfhi(qv.x), hy = bfhi(qv.y), hz = bfhi(qv.z), hw = bfhi(qv.w);
        int w = r * 68 + (c4 >> 1);
        smw[AQH + w]     = pack2bf(hx, hy);
        smw[AQH + w + 1] = pack2bf(hz, hw);
        smw[AQL + w]     = pack2bf(qv.x - hx, qv.y - hy);
        smw[AQL + w + 1] = pack2bf(qv.z - hz, qv.w - hw);
    }

    uint32_t shb = (uint32_t)__cvta_generic_to_shared(sm);
    int la = lane & 15, hiq = lane >> 4;
    uint32_t aQH = shb + (uint32_t)((AQH + (wr0 + la) * 68 + hiq * 4) << 2);
    uint32_t aQL = shb + (uint32_t)((AQL + (wr0 + la) * 68 + hiq * 4) << 2);
    uint32_t bKH = shb + (uint32_t)((AKH + la * 68 + hiq * 4) << 2);
    uint32_t bKL = shb + (uint32_t)((AKL + la * 68 + hiq * 4) << 2);
    uint32_t aP  = shb + (uint32_t)((APS + (wr0 + la) * 76 + hiq * 4) << 2);
    int rbv = (lane & 7) + ((lane >> 4) << 3), bhiv = (lane >> 3) & 1;
    uint32_t bV = shb + (uint32_t)((AVT + rbv * 68 + bhiv * 4) << 2);

    float oa[16][4];
#pragma unroll
    for (int i = 0; i < 16; i++)
#pragma unroll
        for (int j = 0; j < 4; j++) oa[i][j] = 0.0f;
    float m0 = -1e30f, m1 = -1e30f, l0 = 0.0f, l1 = 0.0f;

    int ktmax = 2 * qt + 1;
    for (int kt = 0; kt <= ktmax; kt++) {
        int kn0 = kt * 64;
        __syncthreads();
        // K hi/lo + V transposed (tf32)
        for (int i = tid; i < 64 * 32; i += 256) {
            int r = i >> 5, c4 = (i & 31) << 2;
            float4 kv = *(const float4*)&qkv[(size_t)(kn0 + r) * QKVN + DIM + kvh * HD + c4];
            float hx = bfhi(kv.x), hy = bfhi(kv.y), hz = bfhi(kv.z), hw = bfhi(kv.w);
            int w = r * 68 + (c4 >> 1);
            smw[AKH + w]     = pack2bf(hx, hy);
            smw[AKH + w + 1] = pack2bf(hz, hw);
            smw[AKL + w]     = pack2bf(kv.x - hx, kv.y - hy);
            smw[AKL + w + 1] = pack2bf(kv.z - hz, kv.w - hw);
            float4 vv = *(const float4*)&qkv[(size_t)(kn0 + r) * QKVN + DIM + NKV * HD + kvh * HD + c4];
            sm[AVT + (c4 + 0) * 68 + r] = tf32f(vv.x);
            sm[AVT + (c4 + 1) * 68 + r] = tf32f(vv.y);
            sm[AVT + (c4 + 2) * 68 + r] = tf32f(vv.z);
            sm[AVT + (c4 + 3) * 68 + r] = tf32f(vv.w);
        }
        __syncthreads();

        if (qm0 + wr0 + 15 < kn0) continue;   // warp fully masked

        // ---- QK^T: bf16 hi/lo 3-term ----
        float sc[8][4];
#pragma unroll
        for (int i = 0; i < 8; i++)
#pragma unroll
            for (int j = 0; j < 4; j++) sc[i][j] = 0.0f;

#pragma unroll 2
        for (int ks = 0; ks < 8; ks++) {
            uint32_t ah[4], al[4];
            ldm4(ah, aQH + ks * 32);
            ldm4(al, aQL + ks * 32);
#pragma unroll
            for (int npp = 0; npp < 4; npp++) {
                uint32_t bh[4], bl[4];
                ldm4(bh, bKH + (uint32_t)(npp * 16 * 68 * 4) + ks * 32);
                ldm4(bl, bKL + (uint32_t)(npp * 16 * 68 * 4) + ks * 32);
                mma16(sc[2 * npp],     ah, bh[0], bh[2]);
                mma16(sc[2 * npp],     al, bh[0], bh[2]);
                mma16(sc[2 * npp],     ah, bl[0], bl[2]);
                mma16(sc[2 * npp + 1], ah, bh[1], bh[3]);
                mma16(sc[2 * npp + 1], al, bh[1], bh[3]);
                mma16(sc[2 * npp + 1], ah, bl[1], bl[3]);
            }
        }

        // causal mask on diagonal tiles
        if (kt >= 2 * qt) {
#pragma unroll
            for (int nf = 0; nf < 8; nf++) {
                int kc = kn0 + nf * 8 + 2 * tg;
                if (kc > row0)     sc[nf][0] = -1e30f;
                if (kc + 1 > row0) sc[nf][1] = -1e30f;
                if (kc > row1)     sc[nf][2] = -1e30f;
                if (kc + 1 > row1) sc[nf][3] = -1e30f;
            }
        }

        // ---- online softmax ----
        float rm0 = -1e30f, rm1 = -1e30f;
#pragma unroll
        for (int nf = 0; nf < 8; nf++) {
            rm0 = fmaxf(rm0, fmaxf(sc[nf][0], sc[nf][1]));
            rm1 = fmaxf(rm1, fmaxf(sc[nf][2], sc[nf][3]));
        }
        rm0 = fmaxf(rm0, __shfl_xor_sync(0xffffffffu, rm0, 1));
        rm0 = fmaxf(rm0, __shfl_xor_sync(0xffffffffu, rm0, 2));
        rm1 = fmaxf(rm1, __shfl_xor_sync(0xffffffffu, rm1, 1));
        rm1 = fmaxf(rm1, __shfl_xor_sync(0xffffffffu, rm1, 2));
        float mn0 = fmaxf(m0, rm0), mn1 = fmaxf(m1, rm1);
        float fac0 = __expf(m0 - mn0), fac1 = __expf(m1 - mn1);
        float rs0 = 0.0f, rs1 = 0.0f;
#pragma unroll
        for (int nf = 0; nf < 8; nf++) {
            sc[nf][0] = __expf(sc[nf][0] - mn0);
            sc[nf][1] = __expf(sc[nf][1] - mn0);
            sc[nf][2] = __expf(sc[nf][2] - mn1);
            sc[nf][3] = __expf(sc[nf][3] - mn1);
            rs0 += sc[nf][0] + sc[nf][1];
            rs1 += sc[nf][2] + sc[nf][3];
        }
        rs0 += __shfl_xor_sync(0xffffffffu, rs0, 1);
        rs0 += __shfl_xor_sync(0xffffffffu, rs0, 2);
        rs1 += __shfl_xor_sync(0xffffffffu, rs1, 1);
        rs1 += __shfl_xor_sync(0xffffffffu, rs1, 2);
        l0 = l0 * fac0 + rs0; m0 = mn0;
        l1 = l1 * fac1 + rs1; m1 = mn1;
#pragma unroll
        for (int nf = 0; nf < 16; nf++) {
            oa[nf][0] *= fac0; oa[nf][1] *= fac0;
            oa[nf][2] *= fac1; oa[nf][3] *= fac1;
        }

        // write P (tf32) to warp-private smem rows
        __syncwarp();
#pragma unroll
        for (int nf = 0; nf < 8; nf++) {
            *(float2*)&sm[APS + (wr0 + g) * 76 + nf * 8 + 2 * tg] =
                make_float2(tf32f(sc[nf][0]), tf32f(sc[nf][1]));
            *(float2*)&sm[APS + (wr0 + g + 8) * 76 + nf * 8 + 2 * tg] =
                make_float2(tf32f(sc[nf][2]), tf32f(sc[nf][3]));
        }
        __syncwarp();

        // ---- O += P @ V (tf32) ----
#pragma unroll 2
        for (int ks2 = 0; ks2 < 8; ks2++) {
            uint32_t pa[4];
            ldm4(pa, aP + ks2 * 32);
#pragma unroll
            for (int np = 0; np < 8; np++) {
                uint32_t bv[4];
                ldm4(bv, bV + (uint32_t)(np * 16 * 68 * 4) + ks2 * 32);
                mma8(oa[2 * np],     pa, bv[0], bv[1]);
                mma8(oa[2 * np + 1], pa, bv[2], bv[3]);
            }
        }
    }

    // epilogue
    float inv0 = 1.0f / l0, inv1 = 1.0f / l1;
#pragma unroll
    for (int nf = 0; nf < 16; nf++) {
        int col = nf * 8 + 2 * tg;
        *(float2*)&O[((size_t)row0 * NH + h) * HD + col] =
            make_float2(oa[nf][0] * inv0, oa[nf][1] * inv0);
        *(float2*)&O[((size_t)row1 * NH + h) * HD + col] =
            make_float2(oa[nf][2] * inv1, oa[nf][3] * inv1);
    }
}

// ---------------- launch ----------------
extern "C" void kernel_launch(void* const* d_in, const int* in_sizes, int n_in,
                              void* d_out, int out_size)
{
    const float* x  = (const float*)d_in[0];
    const float* wq = (const float*)d_in[1];
    const float* wk = (const float*)d_in[2];
    const float* wv = (const float*)d_in[3];
    const float* wo = (const float*)d_in[4];
    const float* fc = (const float*)d_in[5];
    const float* fs = (const float*)d_in[6];
    float* out = (float*)d_out;

    float *qkv, *att;
    cudaGetSymbolAddress((void**)&qkv, g_qkv);
    cudaGetSymbolAddress((void**)&att, g_att);

    int gsh = 2 * BUFE * (int)sizeof(uint32_t);
    cudaFuncSetAttribute(gemm_tf32, cudaFuncAttributeMaxDynamicSharedMemorySize, gsh);

    dim3 blk(256);
    // fused QKV projection: one grid, per-block B-pointer select
    gemm_tf32<<<dim3(QKVN / 128, SEQ / 128), blk, gsh>>>(x, wq, wk, wv, qkv, SEQ, QKVN, DIM);

    // RoPE on q and k sections of fused buffer
    rope_kernel<<<(SEQ * NH * 64 + 255) / 256, 256>>>(qkv, fc, fs, NH, QKVN, SEQ * NH * 64);
    rope_kernel<<<(SEQ * NKV * 64 + 255) / 256, 256>>>(qkv + DIM, fc, fs, NKV, QKVN, SEQ * NKV * 64);

    // attention
    int ash = ATT_WORDS * (int)sizeof(float);
    cudaFuncSetAttribute(attn_tc, cudaFuncAttributeMaxDynamicSharedMemorySize, ash);
    attn_tc<<<dim3(SEQ / 128, NH), blk, ash>>>(qkv, att);

    // output projection (all three B pointers = wo; tiles select B0 since n0 < DIM)
    gemm_tf32<<<dim3(DIM / 128, SEQ / 128), blk, gsh>>>(att, wo, wo, wo, out, SEQ, DIM, DIM);
}

// round 6
// speedup vs baseline: 1.4120x; 1.1073x over previous
#include <cuda_runtime.h>
#include <cuda_bf16.h>
#include <cstdint>

#define SEQ 2048
#define DIM 4096
#define NH  32
#define NKV 8
#define HD  128
#define QKVN 6144   // fused projection N (4096 q + 1024 k + 1024 v)

// ---------------- scratch (device globals: no allocation allowed) ----------------
__device__ float    g_qkv[(size_t)SEQ * QKVN];       // fused q|k|v (fp32)
__device__ float    g_att[(size_t)SEQ * DIM];        // attention out
__device__ uint32_t g_qh[(size_t)NH  * SEQ * 64];    // Q hi  bf16x2 (scaled, roped)
__device__ uint32_t g_ql[(size_t)NH  * SEQ * 64];    // Q lo  bf16x2
__device__ uint32_t g_kh[(size_t)NKV * SEQ * 64];    // K hi  bf16x2 (roped)
__device__ uint32_t g_kl[(size_t)NKV * SEQ * 64];    // K lo  bf16x2
__device__ float    g_vt[(size_t)NKV * HD * SEQ];    // V transposed [c][s], tf32

__device__ __forceinline__ uint32_t cvt_tf32(float x) {
    uint32_t r;
    asm("cvt.rna.tf32.f32 %0, %1;" : "=r"(r) : "f"(x));
    return r;
}
__device__ __forceinline__ float tf32f(float x) { return __uint_as_float(cvt_tf32(x)); }
__device__ __forceinline__ void ldm4(uint32_t* r, uint32_t addr) {
    asm volatile("ldmatrix.sync.aligned.m8n8.x4.shared.b16 {%0,%1,%2,%3}, [%4];"
                 : "=r"(r[0]), "=r"(r[1]), "=r"(r[2]), "=r"(r[3]) : "r"(addr));
}
__device__ __forceinline__ void ldm2(uint32_t* r, uint32_t addr) {
    asm volatile("ldmatrix.sync.aligned.m8n8.x2.shared.b16 {%0,%1}, [%2];"
                 : "=r"(r[0]), "=r"(r[1]) : "r"(addr));
}
__device__ __forceinline__ void mma8(float* c, const uint32_t* a, uint32_t b0, uint32_t b1) {
    asm volatile("mma.sync.aligned.m16n8k8.row.col.f32.tf32.tf32.f32 "
                 "{%0,%1,%2,%3}, {%4,%5,%6,%7}, {%8,%9}, {%0,%1,%2,%3};"
                 : "+f"(c[0]), "+f"(c[1]), "+f"(c[2]), "+f"(c[3])
                 : "r"(a[0]), "r"(a[1]), "r"(a[2]), "r"(a[3]), "r"(b0), "r"(b1));
}
__device__ __forceinline__ void mma16(float* c, const uint32_t* a, uint32_t b0, uint32_t b1) {
    asm volatile("mma.sync.aligned.m16n8k16.row.col.f32.bf16.bf16.f32 "
                 "{%0,%1,%2,%3}, {%4,%5,%6,%7}, {%8,%9}, {%0,%1,%2,%3};"
                 : "+f"(c[0]), "+f"(c[1]), "+f"(c[2]), "+f"(c[3])
                 : "r"(a[0]), "r"(a[1]), "r"(a[2]), "r"(a[3]), "r"(b0), "r"(b1));
}
__device__ __forceinline__ uint32_t pack2bf(float a, float b) {
    __nv_bfloat162 t = __floats2bfloat162_rn(a, b);
    return *(uint32_t*)&t;
}
__device__ __forceinline__ float bfhi(float a) {
    return __bfloat162float(__float2bfloat16(a));
}

// ---------------- TF32 tensor-core NT GEMM (R3 core, fused-B variant) -------------
#define SA 36
#define BUFE (2 * 128 * SA)

__global__ __launch_bounds__(256, 1) void gemm_tf32(const float* __restrict__ A,
                                                    const float* __restrict__ B0,
                                                    const float* __restrict__ B1,
                                                    const float* __restrict__ B2,
                                                    float* __restrict__ C,
                                                    int M, int outN, int K)
{
    extern __shared__ uint32_t sh[];
    int tid = threadIdx.x;
    int wid = tid >> 5, lane = tid & 31;
    int warp_m = wid >> 2, warp_n = wid & 3;
    int m0 = blockIdx.y * 128, n0 = blockIdx.x * 128;

    const float* Bsel;
    int nloc;
    if (n0 < DIM)                { Bsel = B0; nloc = n0; }
    else if (n0 < DIM + 1024)    { Bsel = B1; nloc = n0 - DIM; }
    else                         { Bsel = B2; nloc = n0 - DIM - 1024; }

    int lr = tid >> 3;
    int lc = (tid & 7) * 4;
    const float* Aq = A + (size_t)(m0 + lr) * K + lc;
    const float* Bq = Bsel + (size_t)(nloc + lr) * K + lc;

    float ra[4][4], rb[4][4];
    uint32_t shbase = (uint32_t)__cvta_generic_to_shared(sh);

    uint32_t a_addr[4], b_addr[4];
    {
        int la = lane & 15;
        int ahi = (lane >> 4) & 1;
#pragma unroll
        for (int mi = 0; mi < 4; mi++) {
            int r = warp_m * 64 + mi * 16 + la;
            a_addr[mi] = shbase + (uint32_t)((r * SA + ahi * 4) * 4);
        }
        int lb = lane & 7;
        int bhi = (lane >> 3) & 1;
#pragma unroll
        for (int ni = 0; ni < 4; ni++) {
            int r = warp_n * 32 + ni * 8 + lb;
            b_addr[ni] = shbase + (uint32_t)((128 * SA + r * SA + (bhi & 1) * 4) * 4);
        }
    }

    float acc[4][4][4];
#pragma unroll
    for (int mi = 0; mi < 4; mi++)
#pragma unroll
        for (int ni = 0; ni < 4; ni++)
#pragma unroll
            for (int t = 0; t < 4; t++) acc[mi][ni][t] = 0.0f;

    const int iters = K >> 5;

#pragma unroll
    for (int rr = 0; rr < 4; rr++) {
        float4 a = *(const float4*)(Aq + (size_t)rr * 32 * K);
        ra[rr][0] = a.x; ra[rr][1] = a.y; ra[rr][2] = a.z; ra[rr][3] = a.w;
        float4 b = *(const float4*)(Bq + (size_t)rr * 32 * K);
        rb[rr][0] = b.x; rb[rr][1] = b.y; rb[rr][2] = b.z; rb[rr][3] = b.w;
    }
#pragma unroll
    for (int rr = 0; rr < 4; rr++) {
        uint32_t* As = sh;
        uint32_t* Bs = sh + 128 * SA;
        uint4 av = make_uint4(cvt_tf32(ra[rr][0]), cvt_tf32(ra[rr][1]),
                              cvt_tf32(ra[rr][2]), cvt_tf32(ra[rr][3]));
        *(uint4*)&As[(lr + 32 * rr) * SA + lc] = av;
        uint4 bv = make_uint4(cvt_tf32(rb[rr][0]), cvt_tf32(rb[rr][1]),
                              cvt_tf32(rb[rr][2]), cvt_tf32(rb[rr][3]));
        *(uint4*)&Bs[(lr + 32 * rr) * SA + lc] = bv;
    }
    __syncthreads();

    for (int it = 0; it < iters; ++it) {
        int cur = it & 1;
        if (it + 1 < iters) {
            int ko = (it + 1) << 5;
#pragma unroll
            for (int rr = 0; rr < 4; rr++) {
                float4 a = *(const float4*)(Aq + (size_t)rr * 32 * K + ko);
                ra[rr][0] = a.x; ra[rr][1] = a.y; ra[rr][2] = a.z; ra[rr][3] = a.w;
                float4 b = *(const float4*)(Bq + (size_t)rr * 32 * K + ko);
                rb[rr][0] = b.x; rb[rr][1] = b.y; rb[rr][2] = b.z; rb[rr][3] = b.w;
            }
        }

        uint32_t boff = (uint32_t)(cur * BUFE * 4);
#pragma unroll
        for (int ks = 0; ks < 4; ks++) {
            uint32_t af[4][4], bf2[4][2];
#pragma unroll
            for (int mi = 0; mi < 4; mi++)
                ldm4(af[mi], a_addr[mi] + boff + ks * 32);
#pragma unroll
            for (int ni = 0; ni < 4; ni++)
                ldm2(bf2[ni], b_addr[ni] + boff + ks * 32);
#pragma unroll
            for (int mi = 0; mi < 4; mi++)
#pragma unroll
                for (int ni = 0; ni < 4; ni++)
                    mma8(acc[mi][ni], af[mi], bf2[ni][0], bf2[ni][1]);
        }

        if (it + 1 < iters) {
            uint32_t* As = sh + (cur ^ 1) * BUFE;
            uint32_t* Bs = As + 128 * SA;
#pragma unroll
            for (int rr = 0; rr < 4; rr++) {
                uint4 av = make_uint4(cvt_tf32(ra[rr][0]), cvt_tf32(ra[rr][1]),
                                      cvt_tf32(ra[rr][2]), cvt_tf32(ra[rr][3]));
                *(uint4*)&As[(lr + 32 * rr) * SA + lc] = av;
                uint4 bv = make_uint4(cvt_tf32(rb[rr][0]), cvt_tf32(rb[rr][1]),
                                      cvt_tf32(rb[rr][2]), cvt_tf32(rb[rr][3]));
                *(uint4*)&Bs[(lr + 32 * rr) * SA + lc] = bv;
            }
            __syncthreads();
        }
    }

    int g = lane >> 2, tg = lane & 3;
#pragma unroll
    for (int mi = 0; mi < 4; mi++) {
#pragma unroll
        for (int ni = 0; ni < 4; ni++) {
            int row = m0 + warp_m * 64 + mi * 16 + g;
            int col = n0 + warp_n * 32 + ni * 8 + tg * 2;
            *(float2*)&C[(size_t)row * outN + col] =
                make_float2(acc[mi][ni][0], acc[mi][ni][1]);
            *(float2*)&C[(size_t)(row + 8) * outN + col] =
                make_float2(acc[mi][ni][2], acc[mi][ni][3]);
        }
    }
}

// ---------------- RoPE + operand-format prepasses ----------------
__global__ void rope_q_prep(const float* __restrict__ qkv, const float* __restrict__ cs,
                            const float* __restrict__ sn,
                            uint32_t* __restrict__ qh, uint32_t* __restrict__ ql)
{
    const float scale = 0.08838834764831845f;
    int idx = blockIdx.x * blockDim.x + threadIdx.x;
    if (idx >= SEQ * NH * 64) return;
    int pr = idx & 63;
    int hh = (idx >> 6) & 31;
    int ss = idx >> 11;
    float c = cs[ss * 64 + pr], si = sn[ss * 64 + pr];
    float2 ri = *(const float2*)&qkv[(size_t)ss * QKVN + hh * HD + 2 * pr];
    float ox = (ri.x * c - ri.y * si) * scale;
    float oy = (ri.x * si + ri.y * c) * scale;
    float hx = bfhi(ox), hy = bfhi(oy);
    size_t w = ((size_t)hh * SEQ + ss) * 64 + pr;
    qh[w] = pack2bf(hx, hy);
    ql[w] = pack2bf(ox - hx, oy - hy);
}

__global__ void rope_k_prep(const float* __restrict__ qkv, const float* __restrict__ cs,
                            const float* __restrict__ sn,
                            uint32_t* __restrict__ kh, uint32_t* __restrict__ kl)
{
    int idx = blockIdx.x * blockDim.x + threadIdx.x;
    if (idx >= SEQ * NKV * 64) return;
    int pr = idx & 63;
    int hh = (idx >> 6) & 7;
    int ss = idx >> 9;
    float c = cs[ss * 64 + pr], si = sn[ss * 64 + pr];
    float2 ri = *(const float2*)&qkv[(size_t)ss * QKVN + DIM + hh * HD + 2 * pr];
    float ox = ri.x * c - ri.y * si;
    float oy = ri.x * si + ri.y * c;
    float hx = bfhi(ox), hy = bfhi(oy);
    size_t w = ((size_t)hh * SEQ + ss) * 64 + pr;
    kh[w] = pack2bf(hx, hy);
    kl[w] = pack2bf(ox - hx, oy - hy);
}

// V transpose: [s][c] -> [c][s], tf32-rounded
__global__ void v_prep(const float* __restrict__ qkv, float* __restrict__ vt)
{
    __shared__ float t[32][33];
    int s0 = blockIdx.x * 32, c0 = blockIdx.y * 32;
    int tx = threadIdx.x, ty = threadIdx.y;
#pragma unroll
    for (int j = 0; j < 32; j += 8)
        t[ty + j][tx] = qkv[(size_t)(s0 + ty + j) * QKVN + DIM + 1024 + c0 + tx];
    __syncthreads();
#pragma unroll
    for (int j = 0; j < 32; j += 8)
        vt[(size_t)(c0 + ty + j) * SEQ + s0 + tx] = tf32f(t[tx][ty + j]);
}

// ---------------- Tensor-core flash attention: cp.async pipelined ----------------
// smem words (4B): QH 128x68 | QL 128x68 | KH 2x64x68 | KL 2x64x68 | VT 128x68 | PS 128x68
#define AQH 0
#define AQL 8704
#define AKH 17408
#define AKL 26112
#define KSTG 4352
#define AVT 34816
#define APS 43520
#define ATT_WORDS 52224    // 208896 bytes

__global__ __launch_bounds__(256, 1) void attn_tc(const uint32_t* __restrict__ qh,
                                                  const uint32_t* __restrict__ ql,
                                                  const uint32_t* __restrict__ kh,
                                                  const uint32_t* __restrict__ kl,
                                                  const float* __restrict__ vt,
                                                  float* __restrict__ O)
{
    extern __shared__ float sm[];
    int tid = threadIdx.x, wid = tid >> 5, lane = tid & 31;
    int qt = (int)gridDim.x - 1 - (int)blockIdx.x;   // longest-first
    int h = blockIdx.y, kvh = h >> 2;
    int qm0 = qt * 128;
    int g = lane >> 2, tg = lane & 3;
    int wr0 = wid * 16;
    int row0 = qm0 + wr0 + g, row1 = row0 + 8;

    uint32_t shb = (uint32_t)__cvta_generic_to_shared(sm);

    // ---- prologue: issue Q tile + K tile 0 ----
    {
        const uint32_t* qsrc_h = qh + ((size_t)h * SEQ + qm0) * 64;
        const uint32_t* qsrc_l = ql + ((size_t)h * SEQ + qm0) * 64;
        for (int i = tid; i < 2048; i += 256) {
            int r = i >> 4, ch = (i & 15) * 4;
            asm volatile("cp.async.cg.shared.global [%0], [%1], 16;"
                         :: "r"(shb + ((AQH + r * 68 + ch) << 2)), "l"(qsrc_h + r * 64 + ch));
            asm volatile("cp.async.cg.shared.global [%0], [%1], 16;"
                         :: "r"(shb + ((AQL + r * 68 + ch) << 2)), "l"(qsrc_l + r * 64 + ch));
        }
        const uint32_t* ksrc_h = kh + (size_t)kvh * SEQ * 64;
        const uint32_t* ksrc_l = kl + (size_t)kvh * SEQ * 64;
        for (int i = tid; i < 1024; i += 256) {
            int r = i >> 4, ch = (i & 15) * 4;
            asm volatile("cp.async.cg.shared.global [%0], [%1], 16;"
                         :: "r"(shb + ((AKH + r * 68 + ch) << 2)), "l"(ksrc_h + r * 64 + ch));
            asm volatile("cp.async.cg.shared.global [%0], [%1], 16;"
                         :: "r"(shb + ((AKL + r * 68 + ch) << 2)), "l"(ksrc_l + r * 64 + ch));
        }
        asm volatile("cp.async.commit_group;");
    }

    // fragment smem addresses
    int la = lane & 15, hiq = lane >> 4;
    uint32_t aQH = shb + (uint32_t)((AQH + (wr0 + la) * 68 + hiq * 4) << 2);
    uint32_t aQL = shb + (uint32_t)((AQL + (wr0 + la) * 68 + hiq * 4) << 2);
    uint32_t bKHb = shb + (uint32_t)((AKH + la * 68 + hiq * 4) << 2);
    uint32_t bKLb = shb + (uint32_t)((AKL + la * 68 + hiq * 4) << 2);
    uint32_t aP  = shb + (uint32_t)((APS + (wr0 + la) * 68 + hiq * 4) << 2);
    int rbv = (lane & 7) + ((lane >> 4) << 3), bhiv = (lane >> 3) & 1;
    uint32_t bV = shb + (uint32_t)((AVT + rbv * 68 + bhiv * 4) << 2);

    float oa[16][4];
#pragma unroll
    for (int i = 0; i < 16; i++)
#pragma unroll
        for (int j = 0; j < 4; j++) oa[i][j] = 0.0f;
    float m0 = -1e30f, m1 = -1e30f, l0 = 0.0f, l1 = 0.0f;

    int ktmax = 2 * qt + 1;
    const uint32_t* ksrc_h = kh + (size_t)kvh * SEQ * 64;
    const uint32_t* ksrc_l = kl + (size_t)kvh * SEQ * 64;
    const float*    vsrc   = vt + (size_t)kvh * HD * SEQ;

    for (int kt = 0; kt <= ktmax; kt++) {
        int kn0 = kt * 64;
        int st = kt & 1;
        uint32_t stoff = (uint32_t)(st * KSTG * 4);

        __syncthreads();   // V buffer + next K stage free

        // issue V(kt)
        for (int i = tid; i < 2048; i += 256) {
            int c = i >> 4, ch = (i & 15) * 4;
            asm volatile("cp.async.cg.shared.global [%0], [%1], 16;"
                         :: "r"(shb + ((AVT + c * 68 + ch) << 2)),
                            "l"(vsrc + (size_t)c * SEQ + kn0 + ch));
        }
        asm volatile("cp.async.commit_group;");

        // issue K(kt+1)
        if (kt < ktmax) {
            uint32_t nstoff = (uint32_t)((st ^ 1) * KSTG * 4);
            int kn1 = kn0 + 64;
            for (int i = tid; i < 1024; i += 256) {
                int r = i >> 4, ch = (i & 15) * 4;
                asm volatile("cp.async.cg.shared.global [%0], [%1], 16;"
                             :: "r"(shb + ((AKH + r * 68 + ch) << 2) + nstoff),
                                "l"(ksrc_h + (size_t)(kn1 + r) * 64 + ch));
                asm volatile("cp.async.cg.shared.global [%0], [%1], 16;"
                             :: "r"(shb + ((AKL + r * 68 + ch) << 2) + nstoff),
                                "l"(ksrc_l + (size_t)(kn1 + r) * 64 + ch));
            }
        }
        asm volatile("cp.async.commit_group;");

        asm volatile("cp.async.wait_group 2;");   // K(kt) (and Q) ready
        __syncthreads();

        bool skip = (qm0 + wr0 + 15 < kn0);
        float sc[8][4];

        if (!skip) {
            // ---- QK^T: bf16 hi/lo 3-term ----
#pragma unroll
            for (int i = 0; i < 8; i++)
#pragma unroll
                for (int j = 0; j < 4; j++) sc[i][j] = 0.0f;

#pragma unroll 2
            for (int ks = 0; ks < 8; ks++) {
                uint32_t ah[4], al[4];
                ldm4(ah, aQH + ks * 32);
                ldm4(al, aQL + ks * 32);
#pragma unroll
                for (int npp = 0; npp < 4; npp++) {
                    uint32_t bh[4], bl[4];
                    ldm4(bh, bKHb + stoff + (uint32_t)(npp * 16 * 68 * 4) + ks * 32);
                    ldm4(bl, bKLb + stoff + (uint32_t)(npp * 16 * 68 * 4) + ks * 32);
                    mma16(sc[2 * npp],     ah, bh[0], bh[2]);
                    mma16(sc[2 * npp],     al, bh[0], bh[2]);
                    mma16(sc[2 * npp],     ah, bl[0], bl[2]);
                    mma16(sc[2 * npp + 1], ah, bh[1], bh[3]);
                    mma16(sc[2 * npp + 1], al, bh[1], bh[3]);
                    mma16(sc[2 * npp + 1], ah, bl[1], bl[3]);
                }
            }

            // causal mask on diagonal tiles
            if (kt >= 2 * qt) {
#pragma unroll
                for (int nf = 0; nf < 8; nf++) {
                    int kc = kn0 + nf * 8 + 2 * tg;
                    if (kc > row0)     sc[nf][0] = -1e30f;
                    if (kc + 1 > row0) sc[nf][1] = -1e30f;
                    if (kc > row1)     sc[nf][2] = -1e30f;
                    if (kc + 1 > row1) sc[nf][3] = -1e30f;
                }
            }

            // ---- online softmax ----
            float rm0 = -1e30f, rm1 = -1e30f;
#pragma unroll
            for (int nf = 0; nf < 8; nf++) {
                rm0 = fmaxf(rm0, fmaxf(sc[nf][0], sc[nf][1]));
                rm1 = fmaxf(rm1, fmaxf(sc[nf][2], sc[nf][3]));
            }
            rm0 = fmaxf(rm0, __shfl_xor_sync(0xffffffffu, rm0, 1));
            rm0 = fmaxf(rm0, __shfl_xor_sync(0xffffffffu, rm0, 2));
            rm1 = fmaxf(rm1, __shfl_xor_sync(0xffffffffu, rm1, 1));
            rm1 = fmaxf(rm1, __shfl_xor_sync(0xffffffffu, rm1, 2));
            float mn0 = fmaxf(m0, rm0), mn1 = fmaxf(m1, rm1);
            float fac0 = __expf(m0 - mn0), fac1 = __expf(m1 - mn1);
            float rs0 = 0.0f, rs1 = 0.0f;
#pragma unroll
            for (int nf = 0; nf < 8; nf++) {
                sc[nf][0] = __expf(sc[nf][0] - mn0);
                sc[nf][1] = __expf(sc[nf][1] - mn0);
                sc[nf][2] = __expf(sc[nf][2] - mn1);
                sc[nf][3] = __expf(sc[nf][3] - mn1);
                rs0 += sc[nf][0] + sc[nf][1];
                rs1 += sc[nf][2] + sc[nf][3];
            }
            rs0 += __shfl_xor_sync(0xffffffffu, rs0, 1);
            rs0 += __shfl_xor_sync(0xffffffffu, rs0, 2);
            rs1 += __shfl_xor_sync(0xffffffffu, rs1, 1);
            rs1 += __shfl_xor_sync(0xffffffffu, rs1, 2);
            l0 = l0 * fac0 + rs0; m0 = mn0;
            l1 = l1 * fac1 + rs1; m1 = mn1;
#pragma unroll
            for (int nf = 0; nf < 16; nf++) {
                oa[nf][0] *= fac0; oa[nf][1] *= fac0;
                oa[nf][2] *= fac1; oa[nf][3] *= fac1;
            }
        }

        asm volatile("cp.async.wait_group 1;");   // V(kt) ready
        __syncthreads();

        if (!skip) {
            // write P (tf32) to warp-private smem rows
#pragma unroll
            for (int nf = 0; nf < 8; nf++) {
                *(float2*)&sm[APS + (wr0 + g) * 68 + nf * 8 + 2 * tg] =
                    make_float2(tf32f(sc[nf][0]), tf32f(sc[nf][1]));
                *(float2*)&sm[APS + (wr0 + g + 8) * 68 + nf * 8 + 2 * tg] =
                    make_float2(tf32f(sc[nf][2]), tf32f(sc[nf][3]));
            }
            __syncwarp();

            // ---- O += P @ V (tf32) ----
#pragma unroll 2
            for (int ks2 = 0; ks2 < 8; ks2++) {
                uint32_t pa[4];
                ldm4(pa, aP + ks2 * 32);
#pragma unroll
                for (int np = 0; np < 8; np++) {
                    uint32_t bv[4];
                    ldm4(bv, bV + (uint32_t)(np * 16 * 68 * 4) + ks2 * 32);
                    mma8(oa[2 * np],     pa, bv[0], bv[1]);
                    mma8(oa[2 * np + 1], pa, bv[2], bv[3]);
                }
            }
        }
    }

    // epilogue
    float inv0 = 1.0f / l0, inv1 = 1.0f / l1;
#pragma unroll
    for (int nf = 0; nf < 16; nf++) {
        int col = nf * 8 + 2 * tg;
        *(float2*)&O[((size_t)row0 * NH + h) * HD + col] =
            make_float2(oa[nf][0] * inv0, oa[nf][1] * inv0);
        *(float2*)&O[((size_t)row1 * NH + h) * HD + col] =
            make_float2(oa[nf][2] * inv1, oa[nf][3] * inv1);
    }
}

// ---------------- launch ----------------
extern "C" void kernel_launch(void* const* d_in, const int* in_sizes, int n_in,
                              void* d_out, int out_size)
{
    const float* x  = (const float*)d_in[0];
    const float* wq = (const float*)d_in[1];
    const float* wk = (const float*)d_in[2];
    const float* wv = (const float*)d_in[3];
    const float* wo = (const float*)d_in[4];
    const float* fc = (const float*)d_in[5];
    const float* fs = (const float*)d_in[6];
    float* out = (float*)d_out;

    float *qkv, *att, *vtb;
    uint32_t *qhb, *qlb, *khb, *klb;
    cudaGetSymbolAddress((void**)&qkv, g_qkv);
    cudaGetSymbolAddress((void**)&att, g_att);
    cudaGetSymbolAddress((void**)&qhb, g_qh);
    cudaGetSymbolAddress((void**)&qlb, g_ql);
    cudaGetSymbolAddress((void**)&khb, g_kh);
    cudaGetSymbolAddress((void**)&klb, g_kl);
    cudaGetSymbolAddress((void**)&vtb, g_vt);

    int gsh = 2 * BUFE * (int)sizeof(uint32_t);
    cudaFuncSetAttribute(gemm_tf32, cudaFuncAttributeMaxDynamicSharedMemorySize, gsh);

    dim3 blk(256);
    // fused QKV projection
    gemm_tf32<<<dim3(QKVN / 128, SEQ / 128), blk, gsh>>>(x, wq, wk, wv, qkv, SEQ, QKVN, DIM);

    // prepasses: rope + hi/lo split; V transpose
    rope_q_prep<<<(SEQ * NH * 64 + 255) / 256, 256>>>(qkv, fc, fs, qhb, qlb);
    rope_k_prep<<<(SEQ * NKV * 64 + 255) / 256, 256>>>(qkv, fc, fs, khb, klb);
    v_prep<<<dim3(SEQ / 32, 1024 / 32), dim3(32, 8)>>>(qkv, vtb);

    // attention
    int ash = ATT_WORDS * (int)sizeof(float);
    cudaFuncSetAttribute(attn_tc, cudaFuncAttributeMaxDynamicSharedMemorySize, ash);
    attn_tc<<<dim3(SEQ / 128, NH), blk, ash>>>(qhb, qlb, khb, klb, vtb, att);

    // output projection
    gemm_tf32<<<dim3(DIM / 128, SEQ / 128), blk, gsh>>>(att, wo, wo, wo, out, SEQ, DIM, DIM);
}